// round 7
// baseline (speedup 1.0000x reference)
#include <cuda_runtime.h>
#include <math.h>

// Problem constants
#define BB 64
#define SS 512
#define PD 300       // feature dim
#define KK 50        // labels
#define KP 64        // padded labels
#define RR 5
#define NROWS (BB*SS)        // 32768
#define BM 64                // rows per K1 block
#define XSS 304              // xs smem row stride (mult of 4 -> 16B-aligned cp.async rows)
#define CH_ELEMS (150*KP*2)  // 19200 pair-packed chat floats
#define NCH 16               // k3 pooling chunks per batch

// Scratch (device globals; no runtime allocation allowed)
__device__ __align__(16) float g_chat2[CH_ELEMS];    // [pp=150][half=2][tx=16][q=4]
__device__ __align__(16) float g_G[NROWS*KK];        // [row][k] cosine scores
__device__ __align__(16) float g_m[NROWS];           // conv+relu+max over k
__device__ __align__(16) float g_beta[NROWS];        // softmax weights
__device__ __align__(16) float g_part[BB*NCH*PD];    // pooling partials

// ---- packed fp32x2 FMA (Blackwell FFMA2 path) ----
__device__ __forceinline__ void fma2(unsigned long long& d,
                                     unsigned long long a,
                                     unsigned long long b) {
    asm("fma.rn.f32x2 %0, %1, %2, %0;" : "+l"(d) : "l"(a), "l"(b));
}
__device__ __forceinline__ float sum2(unsigned long long v) {
    return __uint_as_float((unsigned)v) + __uint_as_float((unsigned)(v >> 32));
}
__device__ __forceinline__ unsigned s2u(const void* p) {
    unsigned a;
    asm("{ .reg .u64 t; cvta.to.shared.u64 t, %1; cvt.u32.u64 %0, t; }"
        : "=r"(a) : "l"(p));
    return a;
}

// ============================================================
// K0: normalize label embeddings C -> packed g_chat2.
// Per pp (512B row): half=0 holds k pairs {4tx, 4tx+1}, half=1 {4tx+2, 4tx+3},
// each tx owning a contiguous 16B chunk -> coalesced LDG.128 in k1.
// ============================================================
__global__ void k0_chat(const float* __restrict__ C) {
    __shared__ float inv[KP];
    int tid = threadIdx.x;   // 256
    if (tid < KP) {
        float s = 0.f;
        if (tid < KK) {
            const float* row = C + tid * PD;
            for (int p = 0; p < PD; p++) s = fmaf(row[p], row[p], s);
            inv[tid] = 1.f / (sqrtf(s) + 0.001f);
        } else {
            inv[tid] = 0.f;
        }
    }
    __syncthreads();
    for (int i = tid; i < CH_ELEMS; i += 256) {
        int pp   = i >> 7;
        int rem  = i & 127;
        int half = rem >> 6;
        int w    = rem & 63;
        int tx   = w >> 2;
        int q    = w & 3;
        int k    = 4 * tx + 2 * half + (q >> 1);
        int e    = q & 1;
        int p    = 2 * pp + e;
        float v = 0.f;
        if (k < KK) v = C[k * PD + p] * inv[k];
        g_chat2[i] = v;
    }
}

// ============================================================
// K1: gathered cosine-score GEMM.
// Block: 64 rows x 64 k. 256 threads, 4x4 tile/thread.
// A gathered into smem via cp.async; B (chat) read via LDG from
// global -> stays L1-resident (77KB), smem holds only xs -> 2 blocks/SM.
// ============================================================
__global__ void __launch_bounds__(256, 2)
k1_scores(const int* __restrict__ idx, const float* __restrict__ emb) {
    extern __shared__ float xs[];    // BM * XSS
    __shared__ float inv[BM];

    const int tid  = threadIdx.x;
    const int lane = tid & 31;
    const int warp = tid >> 5;
    const int row0 = blockIdx.x * BM;

    // gather x rows via cp.async (batched)
    for (int r = warp; r < BM; r += 8) {
        const float4* src = (const float4*)(emb + (size_t)idx[row0 + r] * PD);
        unsigned dst = s2u(xs + r * XSS);
        #pragma unroll
        for (int i = 0; i < 3; i++) {
            int p4 = lane + 32 * i;
            if (p4 < 75)
                asm volatile("cp.async.cg.shared.global [%0], [%1], 16;"
                             :: "r"(dst + 16u * (unsigned)p4), "l"(src + p4));
        }
    }
    asm volatile("cp.async.commit_group;");
    asm volatile("cp.async.wait_group 0;" ::: "memory");
    __syncthreads();

    // inverse norms from smem (warp per row)
    for (int r = warp; r < BM; r += 8) {
        const float* xr = xs + r * XSS;
        float ss = 0.f;
        #pragma unroll
        for (int i = 0; i < 10; i++) {
            int p = lane + 32 * i;
            if (p < PD) { float v = xr[p]; ss = fmaf(v, v, ss); }
        }
        #pragma unroll
        for (int o = 16; o; o >>= 1) ss += __shfl_xor_sync(0xffffffffu, ss, o);
        if (lane == 0) inv[r] = 1.f / (sqrtf(ss) + 0.001f);
    }
    __syncthreads();

    const int tx = tid & 15;   // k direction (4 k each)
    const int ty = tid >> 4;   // row direction (4 rows each)

    unsigned long long acc[4][4];
    #pragma unroll
    for (int i = 0; i < 4; i++)
        #pragma unroll
        for (int j = 0; j < 4; j++) acc[i][j] = 0ull;

    const float* aBase = xs + (ty * 4) * XSS;
    const ulonglong2* bG = (const ulonglong2*)g_chat2 + tx;  // 16B chunks

    #pragma unroll 2
    for (int pp = 0; pp < 150; pp++) {
        unsigned long long a0 = *(const unsigned long long*)(aBase + 2 * pp);
        unsigned long long a1 = *(const unsigned long long*)(aBase + XSS + 2 * pp);
        unsigned long long a2 = *(const unsigned long long*)(aBase + 2 * XSS + 2 * pp);
        unsigned long long a3 = *(const unsigned long long*)(aBase + 3 * XSS + 2 * pp);
        ulonglong2 B0 = __ldg(bG + pp * 32);        // k = 4tx, 4tx+1
        ulonglong2 B1 = __ldg(bG + pp * 32 + 16);   // k = 4tx+2, 4tx+3
        fma2(acc[0][0], a0, B0.x); fma2(acc[0][1], a0, B0.y);
        fma2(acc[0][2], a0, B1.x); fma2(acc[0][3], a0, B1.y);
        fma2(acc[1][0], a1, B0.x); fma2(acc[1][1], a1, B0.y);
        fma2(acc[1][2], a1, B1.x); fma2(acc[1][3], a1, B1.y);
        fma2(acc[2][0], a2, B0.x); fma2(acc[2][1], a2, B0.y);
        fma2(acc[2][2], a2, B1.x); fma2(acc[2][3], a2, B1.y);
        fma2(acc[3][0], a3, B0.x); fma2(acc[3][1], a3, B0.y);
        fma2(acc[3][2], a3, B1.x); fma2(acc[3][3], a3, B1.y);
    }

    #pragma unroll
    for (int i = 0; i < 4; i++) {
        int row = row0 + ty * 4 + i;
        float iv = inv[ty * 4 + i];
        float* gout = g_G + (size_t)row * KK;
        #pragma unroll
        for (int j = 0; j < 4; j++) {
            int k = tx * 4 + j;
            if (k < KK) gout[k] = sum2(acc[i][j]) * iv;
        }
    }
}

// ============================================================
// K2a: conv(11) + relu + max-over-k.  grid (4 s-tiles, 64 b),
// 128 threads (one per s). Smem tile 138 rows x 51 (halo, stride 51
// odd -> conflict-free). High occupancy, full-chip spread.
// ============================================================
#define GST 51
#define TROWS 138   // 128 + 2*RR

__global__ void __launch_bounds__(128, 8)
k2a_conv(const float* __restrict__ cw, const float* __restrict__ cbp) {
    __shared__ float Gs[TROWS * GST];
    __shared__ float wloc[11];
    __shared__ float cbv_s;

    const int cx = blockIdx.x, b = blockIdx.y, tid = threadIdx.x;
    const int s0 = cx * 128;
    if (tid < 11) wloc[tid] = cw[tid];
    if (tid == 16) cbv_s = cbp[0];

    const float* Gb = g_G + (size_t)b * SS * KK;
    for (int i = tid; i < TROWS * KK; i += 128) {
        int r = i / KK, k = i - r * KK;
        int sr = s0 - RR + r;
        Gs[r * GST + k] = (sr >= 0 && sr < SS) ? Gb[sr * KK + k] : 0.f;
    }
    __syncthreads();

    const float cbv = cbv_s;
    float m = 0.f;   // relu >= 0
    for (int k = 0; k < KK; k++) {
        float v = cbv;
        const float* gp = Gs + tid * GST + k;   // local row of s0+tid-5+j is tid+j
        #pragma unroll
        for (int j = 0; j < 11; j++) v = fmaf(wloc[j], gp[j * GST], v);
        m = fmaxf(m, fmaxf(v, 0.f));
    }
    g_m[b * SS + s0 + tid] = m;
}

// ============================================================
// K2b: softmax over s per batch. 64 blocks x 512 threads.
// ============================================================
__global__ void __launch_bounds__(512, 2)
k2b_softmax() {
    __shared__ float red1[16], red2[16];
    __shared__ float sc[2];
    const int b = blockIdx.x, tid = threadIdx.x;
    const int lane = tid & 31, warp = tid >> 5;

    float m = g_m[b * SS + tid];
    float mx = m;
    #pragma unroll
    for (int o = 16; o; o >>= 1) mx = fmaxf(mx, __shfl_xor_sync(0xffffffffu, mx, o));
    if (lane == 0) red1[warp] = mx;
    __syncthreads();
    if (warp == 0) {
        float v = (lane < 16) ? red1[lane] : -1e30f;
        #pragma unroll
        for (int o = 8; o; o >>= 1) v = fmaxf(v, __shfl_xor_sync(0xffffffffu, v, o));
        if (lane == 0) sc[0] = v;
    }
    __syncthreads();
    float e = expf(m - sc[0]);
    float sum = e;
    #pragma unroll
    for (int o = 16; o; o >>= 1) sum += __shfl_xor_sync(0xffffffffu, sum, o);
    if (lane == 0) red2[warp] = sum;
    __syncthreads();
    if (warp == 0) {
        float v = (lane < 16) ? red2[lane] : 0.f;
        #pragma unroll
        for (int o = 8; o; o >>= 1) v += __shfl_xor_sync(0xffffffffu, v, o);
        if (lane == 0) sc[1] = v;
    }
    __syncthreads();
    g_beta[b * SS + tid] = e / sc[1];
}

// ============================================================
// K3a: pooling partials. grid (16 chunks, 64 b), 320 threads.
// 32 s per block, 8-deep MLP.
// ============================================================
__global__ void __launch_bounds__(320, 4)
k3a_pool(const int* __restrict__ idx, const float* __restrict__ emb) {
    __shared__ float sbeta[32];
    __shared__ int   sidx[32];
    const int cx = blockIdx.x, b = blockIdx.y, tid = threadIdx.x;
    const int s0 = b * SS + cx * 32;
    if (tid < 32) {
        sbeta[tid] = g_beta[s0 + tid];
        sidx[tid]  = idx[s0 + tid];
    }
    __syncthreads();
    if (tid < PD) {
        float a[8];
        #pragma unroll
        for (int i = 0; i < 8; i++) a[i] = 0.f;
        #pragma unroll
        for (int s = 0; s < 32; s += 8) {
            #pragma unroll
            for (int i = 0; i < 8; i++)
                a[i] = fmaf(sbeta[s + i],
                            __ldg(emb + (size_t)sidx[s + i] * PD + tid), a[i]);
        }
        float r = ((a[0] + a[1]) + (a[2] + a[3])) + ((a[4] + a[5]) + (a[6] + a[7]));
        g_part[(b * NCH + cx) * PD + tid] = r;
    }
}

// ============================================================
// K3b: combine partials + final GEMV out = pooled @ W2^T + b2.
// ============================================================
__global__ void __launch_bounds__(320, 4)
k3b_out(const float* __restrict__ W2, const float* __restrict__ b2,
        float* __restrict__ out) {
    __shared__ float pooled[PD];
    const int b = blockIdx.x, tid = threadIdx.x;
    if (tid < PD) {
        float s = 0.f;
        #pragma unroll
        for (int c = 0; c < NCH; c++) s += g_part[(b * NCH + c) * PD + tid];
        pooled[tid] = s * (1.0f / (float)SS);
    }
    __syncthreads();

    const int warp = tid >> 5, lane = tid & 31;  // 10 warps x 5 k
    #pragma unroll
    for (int kk = 0; kk < 5; kk++) {
        int k = warp * 5 + kk;
        float d = 0.f;
        for (int p = lane; p < PD; p += 32) d = fmaf(pooled[p], W2[k * PD + p], d);
        #pragma unroll
        for (int o = 16; o; o >>= 1) d += __shfl_xor_sync(0xffffffffu, d, o);
        if (lane == 0) out[b * KK + k] = d + b2[k];
    }
}

// ============================================================
extern "C" void kernel_launch(void* const* d_in, const int* in_sizes, int n_in,
                              void* d_out, int out_size) {
    const int*   idx    = (const int*)d_in[0];
    const float* emb    = (const float*)d_in[1];
    const float* C      = (const float*)d_in[2];
    const float* conv_w = (const float*)d_in[3];
    const float* conv_b = (const float*)d_in[4];
    const float* W2     = (const float*)d_in[5];
    const float* b2     = (const float*)d_in[6];
    float*       out    = (float*)d_out;

    const int sm1 = BM * XSS * (int)sizeof(float);   // ~76 KB (2 blocks/SM)
    cudaFuncSetAttribute(k1_scores, cudaFuncAttributeMaxDynamicSharedMemorySize, sm1);

    k0_chat<<<1, 256>>>(C);
    k1_scores<<<NROWS / BM, 256, sm1>>>(idx, emb);
    k2a_conv<<<dim3(4, BB), 128>>>(conv_w, conv_b);
    k2b_softmax<<<BB, 512>>>();
    k3a_pool<<<dim3(NCH, BB), 320>>>(idx, emb);
    k3b_out<<<BB, 320>>>(W2, b2, out);
}